// round 9
// baseline (speedup 1.0000x reference)
#include <cuda_runtime.h>
#include <cuda_bf16.h>

#define NB       4096
#define NINPUTS  41024
#define N4       (NINPUTS / 4)     // 10256 float4 per perspective row
#define TOT4     (2 * N4)          // 20512 combined (w then b)
#define LINES    641               // TOT4 / 32 (512B warp-lines)
#define NL1      128
#define NL2      32
#define CAPS     192
#define NT       256
#define U        8                 // float4 loads in flight per thread
#define NBLK     740               // 148 SMs * 5 resident blocks
#define LP       82                // producer lines per warp (7*82 = 574)
#define LC       67                // consumer lines (574 + 67 = 641)
#define PBAT     (LP / U)          // 10 full batches
#define PREM     (LP % U)          // 2 single lines
#define CBAT     (LC / U)          // 8 full batches
#define CREM     (LC % U)          // 3 single lines

__device__ __forceinline__ float clip01(float x) {
    return fminf(fmaxf(x, 0.f), 1.f);
}

// Compact one float4 worth of sparse features into the shared list.
__device__ __forceinline__ void compact4(
    float4 vv, int i, int kb,
    int (*s_e)[CAPS], float (*s_v)[CAPS], int* s_cnt)
{
    if (vv.x != 0.f || vv.y != 0.f || vv.z != 0.f || vv.w != 0.f) {
        const int p   = (i >= N4);
        const int col = (i - p * N4) * 4;
        const int tag = p << 16;
        if (vv.x != 0.f) { int q = atomicAdd(&s_cnt[kb], 1); if (q < CAPS) { s_e[kb][q] = tag | (col + 0); s_v[kb][q] = vv.x; } }
        if (vv.y != 0.f) { int q = atomicAdd(&s_cnt[kb], 1); if (q < CAPS) { s_e[kb][q] = tag | (col + 1); s_v[kb][q] = vv.y; } }
        if (vv.z != 0.f) { int q = atomicAdd(&s_cnt[kb], 1); if (q < CAPS) { s_e[kb][q] = tag | (col + 2); s_v[kb][q] = vv.z; } }
        if (vv.w != 0.f) { int q = atomicAdd(&s_cnt[kb], 1); if (q < CAPS) { s_e[kb][q] = tag | (col + 3); s_v[kb][q] = vv.w; } }
    }
}

// All-warps-scan warp-specialized kernel: every warp owns a contiguous chunk
// of the fused (w,b) row; warp 7's chunk is smaller (67 vs 82 lines) to make
// room for its consumer duties (gather L2-resident W_ft + clipped MLP of the
// previous row, double-buffered). One __syncthreads per row.
__global__ void __launch_bounds__(NT, 5) nnue_ws_kernel(
    const float* __restrict__ us,   const float* __restrict__ them,
    const float* __restrict__ w_in, const float* __restrict__ b_in,
    const float* __restrict__ W_ft, const float* __restrict__ b_ft,
    const float* __restrict__ W1,   const float* __restrict__ b1,
    const float* __restrict__ W2,   const float* __restrict__ b2,
    const float* __restrict__ Wo,   const float* __restrict__ bo,
    float* __restrict__ out)
{
    __shared__ int   s_e[2][CAPS];      // (p<<16) | feature index
    __shared__ float s_v[2][CAPS];
    __shared__ int   s_cnt[2];
    __shared__ float s_l0[2 * NL1];     // consumer-private

    const int tid  = threadIdx.x;
    const int lane = tid & 31;
    const int warp = tid >> 5;
    const bool cons = (warp == 7);

    const int line0 = cons ? 7 * LP : warp * LP;
    const int nbat  = cons ? CBAT : PBAT;
    const int nrem  = cons ? CREM : PREM;

    if (tid < 2) s_cnt[tid] = 0;
    __syncthreads();

    int kb = 0;
    int prev = -1;

    for (int row = blockIdx.x; row < NB; row += gridDim.x) {
        // ---- consumer: process the previous row's buffer first ----
        if (cons && prev >= 0) {
            const int b = kb ^ 1;
            int cnt;
            if (lane == 0) { cnt = s_cnt[b]; s_cnt[b] = 0; }   // latch + reset
            cnt = min(__shfl_sync(0xffffffffu, cnt, 0), CAPS);

            float aw0 = 0.f, aw1 = 0.f, aw2 = 0.f, aw3 = 0.f;
            float ab0 = 0.f, ab1 = 0.f, ab2 = 0.f, ab3 = 0.f;
            #pragma unroll 4
            for (int f = 0; f < cnt; ++f) {
                const int   e   = s_e[b][f];
                const float val = s_v[b][f];
                const float* wr = W_ft + (e & 0xFFFF) * NL1 + lane;
                const float w0 = __ldg(wr);
                const float w1 = __ldg(wr + 32);
                const float w2 = __ldg(wr + 64);
                const float w3 = __ldg(wr + 96);
                if (e & (1 << 16)) {
                    ab0 += val * w0; ab1 += val * w1; ab2 += val * w2; ab3 += val * w3;
                } else {
                    aw0 += val * w0; aw1 += val * w1; aw2 += val * w2; aw3 += val * w3;
                }
            }
            aw0 += __ldg(&b_ft[lane]);       ab0 += __ldg(&b_ft[lane]);
            aw1 += __ldg(&b_ft[lane + 32]);  ab1 += __ldg(&b_ft[lane + 32]);
            aw2 += __ldg(&b_ft[lane + 64]);  ab2 += __ldg(&b_ft[lane + 64]);
            aw3 += __ldg(&b_ft[lane + 96]);  ab3 += __ldg(&b_ft[lane + 96]);

            const float uu = __ldg(&us[prev]);
            const float tt = __ldg(&them[prev]);
            s_l0[lane]             = clip01(uu * aw0 + tt * ab0);
            s_l0[lane + 32]        = clip01(uu * aw1 + tt * ab1);
            s_l0[lane + 64]        = clip01(uu * aw2 + tt * ab2);
            s_l0[lane + 96]        = clip01(uu * aw3 + tt * ab3);
            s_l0[NL1 + lane]       = clip01(uu * ab0 + tt * aw0);
            s_l0[NL1 + lane + 32]  = clip01(uu * ab1 + tt * aw1);
            s_l0[NL1 + lane + 64]  = clip01(uu * ab2 + tt * aw2);
            s_l0[NL1 + lane + 96]  = clip01(uu * ab3 + tt * aw3);
            __syncwarp();

            float a1 = __ldg(&b1[lane]);
            #pragma unroll 8
            for (int i = 0; i < 2 * NL1; ++i)
                a1 += s_l0[i] * __ldg(&W1[i * NL2 + lane]);
            const float l1v = clip01(a1);
            __syncwarp();

            float a2 = __ldg(&b2[lane]);
            #pragma unroll
            for (int i = 0; i < NL2; ++i) {
                const float li = __shfl_sync(0xffffffffu, l1v, i);
                a2 += li * __ldg(&W2[i * NL2 + lane]);
            }
            const float l2v = clip01(a2);

            float r = l2v * __ldg(&Wo[lane]);
            #pragma unroll
            for (int off = 16; off > 0; off >>= 1)
                r += __shfl_down_sync(0xffffffffu, r, off);
            if (lane == 0) out[prev] = r + __ldg(&bo[0]);
        }

        // ---- all warps: scan own chunk of this row into buf[kb] ----
        {
            const float4* __restrict__ w4 = (const float4*)(w_in + (size_t)row * NINPUTS);
            const float4* __restrict__ b4 = (const float4*)(b_in + (size_t)row * NINPUTS);

            #pragma unroll 1
            for (int bt = 0; bt < nbat; ++bt) {
                const int lbase = line0 + bt * U;
                float4 v[U];
                #pragma unroll
                for (int u = 0; u < U; ++u) {
                    const int i = (lbase + u) * 32 + lane;
                    v[u] = __ldcs((i < N4) ? (w4 + i) : (b4 + (i - N4)));
                }
                #pragma unroll
                for (int u = 0; u < U; ++u)
                    compact4(v[u], (lbase + u) * 32 + lane, kb, s_e, s_v, s_cnt);
            }
            #pragma unroll 1
            for (int rr = 0; rr < nrem; ++rr) {
                const int i = (line0 + nbat * U + rr) * 32 + lane;
                const float4 vv = __ldcs((i < N4) ? (w4 + i) : (b4 + (i - N4)));
                compact4(vv, i, kb, s_e, s_v, s_cnt);
            }
        }
        __syncthreads();       // row handoff
        prev = row;
        kb ^= 1;
    }

    // ---- consumer: final row ----
    if (cons) {
        const int b = kb ^ 1;
        int cnt;
        if (lane == 0) cnt = s_cnt[b];
        cnt = min(__shfl_sync(0xffffffffu, cnt, 0), CAPS);

        float aw0 = 0.f, aw1 = 0.f, aw2 = 0.f, aw3 = 0.f;
        float ab0 = 0.f, ab1 = 0.f, ab2 = 0.f, ab3 = 0.f;
        #pragma unroll 4
        for (int f = 0; f < cnt; ++f) {
            const int   e   = s_e[b][f];
            const float val = s_v[b][f];
            const float* wr = W_ft + (e & 0xFFFF) * NL1 + lane;
            const float w0 = __ldg(wr);
            const float w1 = __ldg(wr + 32);
            const float w2 = __ldg(wr + 64);
            const float w3 = __ldg(wr + 96);
            if (e & (1 << 16)) {
                ab0 += val * w0; ab1 += val * w1; ab2 += val * w2; ab3 += val * w3;
            } else {
                aw0 += val * w0; aw1 += val * w1; aw2 += val * w2; aw3 += val * w3;
            }
        }
        aw0 += __ldg(&b_ft[lane]);       ab0 += __ldg(&b_ft[lane]);
        aw1 += __ldg(&b_ft[lane + 32]);  ab1 += __ldg(&b_ft[lane + 32]);
        aw2 += __ldg(&b_ft[lane + 64]);  ab2 += __ldg(&b_ft[lane + 64]);
        aw3 += __ldg(&b_ft[lane + 96]);  ab3 += __ldg(&b_ft[lane + 96]);

        const float uu = __ldg(&us[prev]);
        const float tt = __ldg(&them[prev]);
        s_l0[lane]             = clip01(uu * aw0 + tt * ab0);
        s_l0[lane + 32]        = clip01(uu * aw1 + tt * ab1);
        s_l0[lane + 64]        = clip01(uu * aw2 + tt * ab2);
        s_l0[lane + 96]        = clip01(uu * aw3 + tt * ab3);
        s_l0[NL1 + lane]       = clip01(uu * ab0 + tt * aw0);
        s_l0[NL1 + lane + 32]  = clip01(uu * ab1 + tt * aw1);
        s_l0[NL1 + lane + 64]  = clip01(uu * ab2 + tt * aw2);
        s_l0[NL1 + lane + 96]  = clip01(uu * ab3 + tt * aw3);
        __syncwarp();

        float a1 = __ldg(&b1[lane]);
        #pragma unroll 8
        for (int i = 0; i < 2 * NL1; ++i)
            a1 += s_l0[i] * __ldg(&W1[i * NL2 + lane]);
        const float l1v = clip01(a1);
        __syncwarp();

        float a2 = __ldg(&b2[lane]);
        #pragma unroll
        for (int i = 0; i < NL2; ++i) {
            const float li = __shfl_sync(0xffffffffu, l1v, i);
            a2 += li * __ldg(&W2[i * NL2 + lane]);
        }
        const float l2v = clip01(a2);

        float r = l2v * __ldg(&Wo[lane]);
        #pragma unroll
        for (int off = 16; off > 0; off >>= 1)
            r += __shfl_down_sync(0xffffffffu, r, off);
        if (lane == 0) out[prev] = r + __ldg(&bo[0]);
    }
}

extern "C" void kernel_launch(void* const* d_in, const int* in_sizes, int n_in,
                              void* d_out, int out_size) {
    const float* us   = (const float*)d_in[0];
    const float* them = (const float*)d_in[1];
    const float* w_in = (const float*)d_in[2];
    const float* b_in = (const float*)d_in[3];
    const float* W_ft = (const float*)d_in[4];
    const float* b_ft = (const float*)d_in[5];
    const float* W1   = (const float*)d_in[6];
    const float* b1   = (const float*)d_in[7];
    const float* W2   = (const float*)d_in[8];
    const float* b2   = (const float*)d_in[9];
    const float* Wo   = (const float*)d_in[10];
    const float* bo   = (const float*)d_in[11];
    float* out = (float*)d_out;

    nnue_ws_kernel<<<NBLK, NT>>>(us, them, w_in, b_in, W_ft, b_ft,
                                 W1, b1, W2, b2, Wo, bo, out);
}

// round 11
// speedup vs baseline: 1.0616x; 1.0616x over previous
#include <cuda_runtime.h>
#include <cuda_bf16.h>
#include <cstdint>

#define NB       4096
#define NINPUTS  41024
#define N4       (NINPUTS / 4)       // 10256 float4 per perspective row
#define TOT4     (2 * N4)            // 20512 fused (w then b)
#define NL1      128
#define NL2      32
#define CAPS     192
#define NT       256
#define NPROD    224                 // 7 producer warps
#define S        6                   // cp.async pipeline depth (stages)
#define STAGEB   (NPROD * 16)        // 3584 B per stage
#define NST      ((TOT4 + NPROD - 1) / NPROD)   // 92 stages per row
#define NBLK     888                 // 148 SMs * 6 resident blocks

__device__ __forceinline__ float clip01(float x) {
    return fminf(fmaxf(x, 0.f), 1.f);
}

// Warp-specialized persistent kernel, cp.async producer pipeline:
// warps 0-6 stream both perspective rows through a 6-stage SMEM pipeline
// (LDGSTS keeps ~3KB/warp in flight continuously; low regs -> 6 blocks/SM
// -> 42 scan warps/SM) and compact nonzeros into a double-buffered list.
// Warp 7 (consumer) gathers L2-resident W_ft rows + runs the clipped MLP for
// the previous row. One __syncthreads per row.
__global__ void __launch_bounds__(NT, 6) nnue_cp_kernel(
    const float* __restrict__ us,   const float* __restrict__ them,
    const float* __restrict__ w_in, const float* __restrict__ b_in,
    const float* __restrict__ W_ft, const float* __restrict__ b_ft,
    const float* __restrict__ W1,   const float* __restrict__ b1,
    const float* __restrict__ W2,   const float* __restrict__ b2,
    const float* __restrict__ Wo,   const float* __restrict__ bo,
    float* __restrict__ out)
{
    __shared__ __align__(16) char s_buf[S][STAGEB];
    __shared__ int   s_e[2][CAPS];      // (p<<16) | feature index
    __shared__ float s_v[2][CAPS];
    __shared__ int   s_cnt[2];
    __shared__ float s_l0[2 * NL1];     // consumer-private

    const int tid  = threadIdx.x;
    const int lane = tid & 31;

    if (tid < 2) s_cnt[tid] = 0;
    __syncthreads();

    if (tid < NPROD) {
        // ================= PRODUCER: cp.async streaming scan =================
        unsigned long long pol;
        asm("createpolicy.fractional.L2::evict_first.b64 %0, 1.0;" : "=l"(pol));
        const unsigned sb0 =
            (unsigned)__cvta_generic_to_shared(&s_buf[0][0]) + tid * 16;

        int kb = 0;
        for (int row = blockIdx.x; row < NB; row += gridDim.x) {
            const float* __restrict__ wrow = w_in + (size_t)row * NINPUTS;
            const float* __restrict__ brow = b_in + (size_t)row * NINPUTS;

            // prologue: fill S stages
            #pragma unroll
            for (int st = 0; st < S; ++st) {
                const int i = st * NPROD + tid;               // always < TOT4
                const float* src = (i < N4) ? (wrow + 4 * i)
                                            : (brow + 4 * (i - N4));
                asm volatile(
                    "cp.async.cg.shared.global.L2::cache_hint [%0], [%1], 16, %2, %3;\n\t"
                    "cp.async.commit_group;"
                    :: "r"(sb0 + st * STAGEB), "l"(src), "r"(16), "l"(pol)
                    : "memory");
            }

            int slot = 0;
            #pragma unroll 1
            for (int st = 0; st < NST; ++st) {
                asm volatile("cp.async.wait_group %0;" :: "n"(S - 1) : "memory");

                const float4 vv = *(const float4*)(&s_buf[slot][tid * 16]);

                // compact nonzeros of this stage's element
                if (vv.x != 0.f || vv.y != 0.f || vv.z != 0.f || vv.w != 0.f) {
                    const int i   = st * NPROD + tid;
                    const int p   = (i >= N4);
                    const int col = (i - p * N4) * 4;
                    const int tag = p << 16;
                    if (vv.x != 0.f) { int q = atomicAdd(&s_cnt[kb], 1); if (q < CAPS) { s_e[kb][q] = tag | (col + 0); s_v[kb][q] = vv.x; } }
                    if (vv.y != 0.f) { int q = atomicAdd(&s_cnt[kb], 1); if (q < CAPS) { s_e[kb][q] = tag | (col + 1); s_v[kb][q] = vv.y; } }
                    if (vv.z != 0.f) { int q = atomicAdd(&s_cnt[kb], 1); if (q < CAPS) { s_e[kb][q] = tag | (col + 2); s_v[kb][q] = vv.z; } }
                    if (vv.w != 0.f) { int q = atomicAdd(&s_cnt[kb], 1); if (q < CAPS) { s_e[kb][q] = tag | (col + 3); s_v[kb][q] = vv.w; } }
                }

                // issue stage st+S into the slot just consumed; commit exactly
                // one group per iteration (possibly empty in the tail) to keep
                // the wait_group(S-1) <-> stage-st-complete invariant.
                const int nx = st + S;
                if (nx < NST) {
                    const int i  = nx * NPROD + tid;
                    const int ii = (i < TOT4) ? i : 0;          // clamp
                    const float* src = (ii < N4) ? (wrow + 4 * ii)
                                                 : (brow + 4 * (ii - N4));
                    const int ssz = (i < TOT4) ? 16 : 0;        // OOB -> zero-fill
                    asm volatile(
                        "cp.async.cg.shared.global.L2::cache_hint [%0], [%1], 16, %2, %3;"
                        :: "r"(sb0 + slot * STAGEB), "l"(src), "r"(ssz), "l"(pol)
                        : "memory");
                }
                asm volatile("cp.async.commit_group;" ::: "memory");

                if (++slot == S) slot = 0;
            }
            __syncthreads();       // handoff row to consumer
            kb ^= 1;
        }
    } else {
        // ================= CONSUMER: gather + clipped MLP ================
        int kb = 0;
        for (int row = blockIdx.x; row < NB; row += gridDim.x) {
            __syncthreads();       // wait for producers to finish this row

            int cnt;
            if (lane == 0) { cnt = s_cnt[kb]; s_cnt[kb] = 0; }   // latch + reset
            cnt = min(__shfl_sync(0xffffffffu, cnt, 0), CAPS);

            // Gather: lane owns dims lane, lane+32, lane+64, lane+96.
            // Warp reads one contiguous 512B W_ft row per feature (L2-hit).
            float aw0 = 0.f, aw1 = 0.f, aw2 = 0.f, aw3 = 0.f;
            float ab0 = 0.f, ab1 = 0.f, ab2 = 0.f, ab3 = 0.f;
            #pragma unroll 4
            for (int f = 0; f < cnt; ++f) {
                const int   e   = s_e[kb][f];
                const float val = s_v[kb][f];
                const float* wr = W_ft + (e & 0xFFFF) * NL1 + lane;
                const float w0 = __ldg(wr);
                const float w1 = __ldg(wr + 32);
                const float w2 = __ldg(wr + 64);
                const float w3 = __ldg(wr + 96);
                if (e & (1 << 16)) {
                    ab0 += val * w0; ab1 += val * w1; ab2 += val * w2; ab3 += val * w3;
                } else {
                    aw0 += val * w0; aw1 += val * w1; aw2 += val * w2; aw3 += val * w3;
                }
            }
            aw0 += __ldg(&b_ft[lane]);       ab0 += __ldg(&b_ft[lane]);
            aw1 += __ldg(&b_ft[lane + 32]);  ab1 += __ldg(&b_ft[lane + 32]);
            aw2 += __ldg(&b_ft[lane + 64]);  ab2 += __ldg(&b_ft[lane + 64]);
            aw3 += __ldg(&b_ft[lane + 96]);  ab3 += __ldg(&b_ft[lane + 96]);

            // l0: perspective select + clip. s_l0[0:128]=us-side, [128:256]=them-side
            const float uu = __ldg(&us[row]);
            const float tt = __ldg(&them[row]);
            s_l0[lane]             = clip01(uu * aw0 + tt * ab0);
            s_l0[lane + 32]        = clip01(uu * aw1 + tt * ab1);
            s_l0[lane + 64]        = clip01(uu * aw2 + tt * ab2);
            s_l0[lane + 96]        = clip01(uu * aw3 + tt * ab3);
            s_l0[NL1 + lane]       = clip01(uu * ab0 + tt * aw0);
            s_l0[NL1 + lane + 32]  = clip01(uu * ab1 + tt * aw1);
            s_l0[NL1 + lane + 64]  = clip01(uu * ab2 + tt * aw2);
            s_l0[NL1 + lane + 96]  = clip01(uu * ab3 + tt * aw3);
            __syncwarp();

            // l1 = clip(l0 @ W1 + b1): lane owns output o=lane, 256 terms
            float a1 = __ldg(&b1[lane]);
            #pragma unroll 8
            for (int i = 0; i < 2 * NL1; ++i)
                a1 += s_l0[i] * __ldg(&W1[i * NL2 + lane]);
            const float l1v = clip01(a1);
            __syncwarp();

            // l2 = clip(l1 @ W2 + b2): broadcast l1 via shuffles
            float a2 = __ldg(&b2[lane]);
            #pragma unroll
            for (int i = 0; i < NL2; ++i) {
                const float li = __shfl_sync(0xffffffffu, l1v, i);
                a2 += li * __ldg(&W2[i * NL2 + lane]);
            }
            const float l2v = clip01(a2);

            // out = l2 @ Wo + bo
            float r = l2v * __ldg(&Wo[lane]);
            #pragma unroll
            for (int off = 16; off > 0; off >>= 1)
                r += __shfl_down_sync(0xffffffffu, r, off);
            if (lane == 0) out[row] = r + __ldg(&bo[0]);

            kb ^= 1;
        }
    }
}

extern "C" void kernel_launch(void* const* d_in, const int* in_sizes, int n_in,
                              void* d_out, int out_size) {
    const float* us   = (const float*)d_in[0];
    const float* them = (const float*)d_in[1];
    const float* w_in = (const float*)d_in[2];
    const float* b_in = (const float*)d_in[3];
    const float* W_ft = (const float*)d_in[4];
    const float* b_ft = (const float*)d_in[5];
    const float* W1   = (const float*)d_in[6];
    const float* b1   = (const float*)d_in[7];
    const float* W2   = (const float*)d_in[8];
    const float* b2   = (const float*)d_in[9];
    const float* Wo   = (const float*)d_in[10];
    const float* bo   = (const float*)d_in[11];
    float* out = (float*)d_out;

    nnue_cp_kernel<<<NBLK, NT>>>(us, them, w_in, b_in, W_ft, b_ft,
                                 W1, b1, W2, b2, Wo, bo, out);
}

// round 12
// speedup vs baseline: 1.1296x; 1.0641x over previous
#include <cuda_runtime.h>
#include <cuda_bf16.h>
#include <cstdint>

#define NB       4096
#define NINPUTS  41024
#define N4       (NINPUTS / 4)     // 10256 float4 per perspective row
#define TOT4     (2 * N4)          // 20512 combined (w then b)
#define NL1      128
#define NL2      32
#define CAPS     192
#define NT       256
#define NPROD    224               // 7 producer warps
#define U        8                 // float4 loads in flight per producer thread
#define NBLK     740               // 148 SMs * 5 resident blocks

__device__ __forceinline__ float clip01(float x) {
    return fminf(fmaxf(x, 0.f), 1.f);
}

// Warp-specialized persistent kernel (R6 shape + integer-test drain):
// warps 0-6 stream-scan both perspective rows of row k+1 into a double-
// buffered compaction list while warp 7 gathers L2-resident W_ft rows and
// runs the clipped MLP for row k. Mask values are {0.0f, 1.0f} (bernoulli
// -> float), never -0.0f, so bit-pattern zero tests are exact and much
// cheaper than FSETP chains (drain time bounds per-warp HBM supply).
// 48 regs needed for the 8-deep load batch -> launch_bounds(256,5); do NOT
// tighten (R7 regression).
__global__ void __launch_bounds__(NT, 5) nnue_ws_kernel(
    const float* __restrict__ us,   const float* __restrict__ them,
    const float* __restrict__ w_in, const float* __restrict__ b_in,
    const float* __restrict__ W_ft, const float* __restrict__ b_ft,
    const float* __restrict__ W1,   const float* __restrict__ b1,
    const float* __restrict__ W2,   const float* __restrict__ b2,
    const float* __restrict__ Wo,   const float* __restrict__ bo,
    float* __restrict__ out)
{
    __shared__ int   s_e[2][CAPS];      // (p<<16) | feature index
    __shared__ float s_v[2][CAPS];
    __shared__ int   s_cnt[2];
    __shared__ float s_l0[2 * NL1];     // consumer-private

    const int tid = threadIdx.x;

    if (tid < 2) s_cnt[tid] = 0;
    __syncthreads();

    if (tid < NPROD) {
        // ================= PRODUCER: pure streaming scan =================
        int kb = 0;
        for (int row = blockIdx.x; row < NB; row += gridDim.x) {
            const float4* __restrict__ w4 = (const float4*)(w_in + (size_t)row * NINPUTS);
            const float4* __restrict__ b4 = (const float4*)(b_in + (size_t)row * NINPUTS);

            #pragma unroll 1
            for (int base = 0; base < TOT4; base += NPROD * U) {
                float4 v[U];
                #pragma unroll
                for (int u = 0; u < U; ++u) {
                    const int i = base + u * NPROD + tid;
                    if (i < TOT4) {
                        const float4* p4 = (i < N4) ? (w4 + i) : (b4 + (i - N4));
                        v[u] = __ldcs(p4);       // evict-first: keep W_ft in L2
                    } else {
                        v[u] = make_float4(0.f, 0.f, 0.f, 0.f);
                    }
                }
                #pragma unroll
                for (int u = 0; u < U; ++u) {
                    // integer zero tests: values are {0.0f, 1.0f}, never -0.0f
                    const int ix = __float_as_int(v[u].x);
                    const int iy = __float_as_int(v[u].y);
                    const int iz = __float_as_int(v[u].z);
                    const int iw = __float_as_int(v[u].w);
                    if ((ix | iy | iz | iw) != 0) {
                        const int i   = base + u * NPROD + tid;
                        const int p   = (i >= N4);
                        const int col = (i - p * N4) * 4;
                        const int tag = p << 16;
                        if (ix) { int q = atomicAdd(&s_cnt[kb], 1); if (q < CAPS) { s_e[kb][q] = tag | (col + 0); s_v[kb][q] = v[u].x; } }
                        if (iy) { int q = atomicAdd(&s_cnt[kb], 1); if (q < CAPS) { s_e[kb][q] = tag | (col + 1); s_v[kb][q] = v[u].y; } }
                        if (iz) { int q = atomicAdd(&s_cnt[kb], 1); if (q < CAPS) { s_e[kb][q] = tag | (col + 2); s_v[kb][q] = v[u].z; } }
                        if (iw) { int q = atomicAdd(&s_cnt[kb], 1); if (q < CAPS) { s_e[kb][q] = tag | (col + 3); s_v[kb][q] = v[u].w; } }
                    }
                }
            }
            __syncthreads();       // handoff row k to consumer
            kb ^= 1;
        }
    } else {
        // ================= CONSUMER: gather + clipped MLP ================
        const int lane = tid & 31;
        int kb = 0;
        for (int row = blockIdx.x; row < NB; row += gridDim.x) {
            __syncthreads();       // wait for producers to finish this row

            int cnt;
            if (lane == 0) { cnt = s_cnt[kb]; s_cnt[kb] = 0; }   // latch + reset
            cnt = min(__shfl_sync(0xffffffffu, cnt, 0), CAPS);

            // Gather: lane owns dims lane, lane+32, lane+64, lane+96.
            // Warp reads one contiguous 512B W_ft row per feature (L2-hit).
            float aw0 = 0.f, aw1 = 0.f, aw2 = 0.f, aw3 = 0.f;
            float ab0 = 0.f, ab1 = 0.f, ab2 = 0.f, ab3 = 0.f;
            #pragma unroll 4
            for (int f = 0; f < cnt; ++f) {
                const int   e   = s_e[kb][f];
                const float val = s_v[kb][f];
                const float* wr = W_ft + (e & 0xFFFF) * NL1 + lane;
                const float w0 = __ldg(wr);
                const float w1 = __ldg(wr + 32);
                const float w2 = __ldg(wr + 64);
                const float w3 = __ldg(wr + 96);
                if (e & (1 << 16)) {
                    ab0 += val * w0; ab1 += val * w1; ab2 += val * w2; ab3 += val * w3;
                } else {
                    aw0 += val * w0; aw1 += val * w1; aw2 += val * w2; aw3 += val * w3;
                }
            }
            aw0 += __ldg(&b_ft[lane]);       ab0 += __ldg(&b_ft[lane]);
            aw1 += __ldg(&b_ft[lane + 32]);  ab1 += __ldg(&b_ft[lane + 32]);
            aw2 += __ldg(&b_ft[lane + 64]);  ab2 += __ldg(&b_ft[lane + 64]);
            aw3 += __ldg(&b_ft[lane + 96]);  ab3 += __ldg(&b_ft[lane + 96]);

            // l0: perspective select + clip. s_l0[0:128]=us-side, [128:256]=them-side
            const float uu = __ldg(&us[row]);
            const float tt = __ldg(&them[row]);
            s_l0[lane]             = clip01(uu * aw0 + tt * ab0);
            s_l0[lane + 32]        = clip01(uu * aw1 + tt * ab1);
            s_l0[lane + 64]        = clip01(uu * aw2 + tt * ab2);
            s_l0[lane + 96]        = clip01(uu * aw3 + tt * ab3);
            s_l0[NL1 + lane]       = clip01(uu * ab0 + tt * aw0);
            s_l0[NL1 + lane + 32]  = clip01(uu * ab1 + tt * aw1);
            s_l0[NL1 + lane + 64]  = clip01(uu * ab2 + tt * aw2);
            s_l0[NL1 + lane + 96]  = clip01(uu * ab3 + tt * aw3);
            __syncwarp();

            // l1 = clip(l0 @ W1 + b1): lane owns output o=lane, 256 terms
            float a1 = __ldg(&b1[lane]);
            #pragma unroll 8
            for (int i = 0; i < 2 * NL1; ++i)
                a1 += s_l0[i] * __ldg(&W1[i * NL2 + lane]);
            const float l1v = clip01(a1);
            __syncwarp();

            // l2 = clip(l1 @ W2 + b2): broadcast l1 via shuffles
            float a2 = __ldg(&b2[lane]);
            #pragma unroll
            for (int i = 0; i < NL2; ++i) {
                const float li = __shfl_sync(0xffffffffu, l1v, i);
                a2 += li * __ldg(&W2[i * NL2 + lane]);
            }
            const float l2v = clip01(a2);

            // out = l2 @ Wo + bo
            float r = l2v * __ldg(&Wo[lane]);
            #pragma unroll
            for (int off = 16; off > 0; off >>= 1)
                r += __shfl_down_sync(0xffffffffu, r, off);
            if (lane == 0) out[row] = r + __ldg(&bo[0]);

            kb ^= 1;
        }
    }
}

extern "C" void kernel_launch(void* const* d_in, const int* in_sizes, int n_in,
                              void* d_out, int out_size) {
    const float* us   = (const float*)d_in[0];
    const float* them = (const float*)d_in[1];
    const float* w_in = (const float*)d_in[2];
    const float* b_in = (const float*)d_in[3];
    const float* W_ft = (const float*)d_in[4];
    const float* b_ft = (const float*)d_in[5];
    const float* W1   = (const float*)d_in[6];
    const float* b1   = (const float*)d_in[7];
    const float* W2   = (const float*)d_in[8];
    const float* b2   = (const float*)d_in[9];
    const float* Wo   = (const float*)d_in[10];
    const float* bo   = (const float*)d_in[11];
    float* out = (float*)d_out;

    nnue_ws_kernel<<<NBLK, NT>>>(us, them, w_in, b_in, W_ft, b_ft,
                                 W1, b1, W2, b2, Wo, bo, out);
}